// round 10
// baseline (speedup 1.0000x reference)
#include <cuda_runtime.h>
#include <cuda_bf16.h>
#include <cstdint>
#include <math.h>

// ---- fixed problem shapes ----
#define Hh   64
#define Wd   64
#define Cc   32
#define Hoc  58
#define Woc  58
#define Ff   64
#define Kk   800            // EH*EW*C
#define Pp   26912          // B*Ho*Wo
#define Ppad 27008          // 211 * 128
#define EPSf 1e-7f

// ---- scratch: bf16 hi/lo split (zero-init; GEMM pad rows stay zero) ----
__device__ __nv_bfloat16 g_rot_hi[(size_t)Ppad * Kk];
__device__ __nv_bfloat16 g_rot_lo[(size_t)Ppad * Kk];
__device__ __nv_bfloat16 g_wt_hi[(size_t)Ff * Kk];    // [f][k] == input W layout
__device__ __nv_bfloat16 g_wt_lo[(size_t)Ff * Kk];

// ---- mma.sync m16n8k16 bf16 (base PTX, plain sm_103) ----
__device__ __forceinline__ void mma_bf16(float* d,
                                         uint32_t a0, uint32_t a1, uint32_t a2, uint32_t a3,
                                         uint32_t b0, uint32_t b1) {
    asm volatile(
        "mma.sync.aligned.m16n8k16.row.col.f32.bf16.bf16.f32 "
        "{%0,%1,%2,%3}, {%4,%5,%6,%7}, {%8,%9}, {%0,%1,%2,%3};"
        : "+f"(d[0]), "+f"(d[1]), "+f"(d[2]), "+f"(d[3])
        : "r"(a0), "r"(a1), "r"(a2), "r"(a3), "r"(b0), "r"(b1));
}

// ------------------------------------------------------------------
// Kernel 1: split W -> bf16 hi/lo ([f][k], no transpose: B is n-major/k-contig)
// ------------------------------------------------------------------
__global__ void wt_kernel(const float* __restrict__ W) {
    int idx = blockIdx.x * blockDim.x + threadIdx.x;
    if (idx < Ff * Kk) {
        float v = W[idx];
        __nv_bfloat16 hi = __float2bfloat16(v);
        float lo = v - __bfloat162float(hi);
        g_wt_hi[idx] = hi;
        g_wt_lo[idx] = __float2bfloat16(lo);
    }
}

// ------------------------------------------------------------------
// Kernel 2: orientation + bilinear rotation -> bf16 hi/lo
// one warp per pixel; lane == channel
// ------------------------------------------------------------------
__global__ void rot_kernel(const float* __restrict__ x) {
    const int warp = threadIdx.x >> 5;
    const int lane = threadIdx.x & 31;
    const int pix  = blockIdx.x * 4 + warp;   // Pp % 4 == 0

    __shared__ float sp[4][49 * 33];
    float* patch = sp[warp];

    const int w = pix % Woc;
    const int t = pix / Woc;
    const int h = t % Hoc;
    const int b = t / Hoc;
    const float* xb = x + (((size_t)b * Hh + h) * Wd + w) * Cc;

    float sI = 0.f, sR = 0.f, sC = 0.f;
#pragma unroll
    for (int p = 0; p < 49; ++p) {
        const int i = p / 7, j = p % 7;
        float v = xb[((size_t)i * Wd + j) * Cc + lane];
        patch[p * 33 + lane] = v;
        sI += v;
        sR += (float)i * v;
        sC += (float)j * v;
    }
#pragma unroll
    for (int off = 16; off; off >>= 1) {
        sI += __shfl_xor_sync(0xffffffffu, sI, off);
        sR += __shfl_xor_sync(0xffffffffu, sR, off);
        sC += __shfl_xor_sync(0xffffffffu, sC, off);
    }

    const float denom = sI + EPSf;
    const float cr = sR / denom - 3.0f;
    const float cc = sC / denom - 3.0f;
    const float ang = atan2f(cr, cc + EPSf);
    const float cA = cosf(ang), sA = sinf(ang);
    const float scale = 1.0f + EPSf;
    const float xo = (6.0f - (cA * 6.0f - sA * 6.0f)) * 0.5f;
    const float yo = (6.0f - (sA * 6.0f + cA * 6.0f)) * 0.5f;
    const float a0 =  cA / scale, a1 = -sA / scale, a2 = xo / scale;
    const float a3 =  sA / scale, a4 =  cA / scale, a5 = yo / scale;

    __nv_bfloat16* oh = g_rot_hi + (size_t)pix * Kk;
    __nv_bfloat16* ol = g_rot_lo + (size_t)pix * Kk;

#pragma unroll
    for (int eh = 0; eh < 5; ++eh) {
        const float yg = (float)(eh + 1);   // crop PAD=1
#pragma unroll
        for (int ew = 0; ew < 5; ++ew) {
            const float xg  = (float)(ew + 1);
            const float xin = a0 * xg + a1 * yg + a2;
            const float yin = a3 * xg + a4 * yg + a5;
            const float x0f = floorf(xin), y0f = floorf(yin);
            const float wx1 = xin - x0f, wx0 = 1.0f - wx1;
            const float wy1 = yin - y0f, wy0 = 1.0f - wy1;
            const int x0 = (int)x0f, y0 = (int)y0f;
            const int x1 = x0 + 1,  y1 = y0 + 1;
            const bool vx0 = (x0 >= 0) & (x0 < 7);
            const bool vx1 = (x1 >= 0) & (x1 < 7);
            const bool vy0 = (y0 >= 0) & (y0 < 7);
            const bool vy1 = (y1 >= 0) & (y1 < 7);
            const float w00 = (vy0 & vx0) ? wy0 * wx0 : 0.f;
            const float w01 = (vy0 & vx1) ? wy0 * wx1 : 0.f;
            const float w10 = (vy1 & vx0) ? wy1 * wx0 : 0.f;
            const float w11 = (vy1 & vx1) ? wy1 * wx1 : 0.f;
            const int x0c = min(max(x0, 0), 6), x1c = min(max(x1, 0), 6);
            const int y0c = min(max(y0, 0), 6), y1c = min(max(y1, 0), 6);
            float r = w00 * patch[(y0c * 7 + x0c) * 33 + lane]
                    + w01 * patch[(y0c * 7 + x1c) * 33 + lane]
                    + w10 * patch[(y1c * 7 + x0c) * 33 + lane]
                    + w11 * patch[(y1c * 7 + x1c) * 33 + lane];
            __nv_bfloat16 hi = __float2bfloat16(r);
            float lo = r - __bfloat162float(hi);
            const int kk = (eh * 5 + ew) * 32 + lane;
            oh[kk] = hi;
            ol[kk] = __float2bfloat16(lo);
        }
    }
}

// ------------------------------------------------------------------
// Kernel 3: HMMA GEMM  out[P x 64] = (Ah+Al)(Bh+Bl)^T + bias  (3 passes)
// BM=128 BN=64 BK=32, 8 warps, warp tile 32x32 (2 x m16  x  4 x n8)
// smem pitch 40 halves (80B): conflict-free fragment LDS
// ------------------------------------------------------------------
#define PITCH 40
#define NCH   25   // 800 / 32

__global__ __launch_bounds__(256) void gemm_mma_kernel(const float* __restrict__ bias,
                                                       float* __restrict__ out) {
    __shared__ __nv_bfloat16 Ah[128 * PITCH], Al[128 * PITCH];
    __shared__ __nv_bfloat16 Bh[ 64 * PITCH], Bl[ 64 * PITCH];

    const int tid  = threadIdx.x;
    const int m0   = blockIdx.x * 128;
    const int warp = tid >> 5, lane = tid & 31;
    const int wm   = warp >> 1, wn = warp & 1;     // warp grid 4 x 2
    const int g    = lane >> 2, tig = lane & 3;

    float acc[2][4][4];
#pragma unroll
    for (int mt = 0; mt < 2; ++mt)
#pragma unroll
        for (int nt = 0; nt < 4; ++nt)
#pragma unroll
            for (int i = 0; i < 4; ++i) acc[mt][nt][i] = 0.f;

    for (int ch = 0; ch < NCH; ++ch) {
        const int k0 = ch * 32;
        // A tiles: 128 rows x 32 bf16 (64B) -> 512 x 16B ; 2 per thread
#pragma unroll
        for (int it = 0; it < 2; ++it) {
            const int u = tid + it * 256;
            const int row = u >> 2, q = u & 3;
            const size_t src = (size_t)(m0 + row) * Kk + k0 + q * 8;
            *(uint4*)&Ah[row * PITCH + q * 8] = *(const uint4*)(g_rot_hi + src);
            *(uint4*)&Al[row * PITCH + q * 8] = *(const uint4*)(g_rot_lo + src);
        }
        // B tiles: 64 rows x 32 bf16 -> 256 x 16B ; 1 per thread
        {
            const int row = tid >> 2, q = tid & 3;
            const size_t src = (size_t)row * Kk + k0 + q * 8;
            *(uint4*)&Bh[row * PITCH + q * 8] = *(const uint4*)(g_wt_hi + src);
            *(uint4*)&Bl[row * PITCH + q * 8] = *(const uint4*)(g_wt_lo + src);
        }
        __syncthreads();

#pragma unroll
        for (int h = 0; h < 2; ++h) {          // two k16 halves of BK=32
            uint32_t afh[2][4], afl[2][4], bfh[4][2], bfl[4][2];
#pragma unroll
            for (int mt = 0; mt < 2; ++mt) {
                const int base = (wm * 32 + mt * 16 + g) * PITCH + h * 16 + tig * 2;
                afh[mt][0] = *(const uint32_t*)&Ah[base];
                afh[mt][1] = *(const uint32_t*)&Ah[base + 8 * PITCH];
                afh[mt][2] = *(const uint32_t*)&Ah[base + 8];
                afh[mt][3] = *(const uint32_t*)&Ah[base + 8 * PITCH + 8];
                afl[mt][0] = *(const uint32_t*)&Al[base];
                afl[mt][1] = *(const uint32_t*)&Al[base + 8 * PITCH];
                afl[mt][2] = *(const uint32_t*)&Al[base + 8];
                afl[mt][3] = *(const uint32_t*)&Al[base + 8 * PITCH + 8];
            }
#pragma unroll
            for (int nt = 0; nt < 4; ++nt) {
                const int base = (wn * 32 + nt * 8 + g) * PITCH + h * 16 + tig * 2;
                bfh[nt][0] = *(const uint32_t*)&Bh[base];
                bfh[nt][1] = *(const uint32_t*)&Bh[base + 8];
                bfl[nt][0] = *(const uint32_t*)&Bl[base];
                bfl[nt][1] = *(const uint32_t*)&Bl[base + 8];
            }
#pragma unroll
            for (int mt = 0; mt < 2; ++mt)
#pragma unroll
                for (int nt = 0; nt < 4; ++nt) {
                    mma_bf16(acc[mt][nt], afh[mt][0], afh[mt][1], afh[mt][2], afh[mt][3],
                             bfh[nt][0], bfh[nt][1]);
                    mma_bf16(acc[mt][nt], afh[mt][0], afh[mt][1], afh[mt][2], afh[mt][3],
                             bfl[nt][0], bfl[nt][1]);
                    mma_bf16(acc[mt][nt], afl[mt][0], afl[mt][1], afl[mt][2], afl[mt][3],
                             bfh[nt][0], bfh[nt][1]);
                }
        }
        __syncthreads();
    }

    // epilogue
#pragma unroll
    for (int mt = 0; mt < 2; ++mt)
#pragma unroll
        for (int nt = 0; nt < 4; ++nt) {
            const int f = wn * 32 + nt * 8 + tig * 2;
            const float2 bb = *(const float2*)(bias + f);
            int m = m0 + wm * 32 + mt * 16 + g;
            if (m < Pp) {
                float2 r = {acc[mt][nt][0] + bb.x, acc[mt][nt][1] + bb.y};
                *(float2*)(out + (size_t)m * Ff + f) = r;
            }
            m += 8;
            if (m < Pp) {
                float2 r = {acc[mt][nt][2] + bb.x, acc[mt][nt][3] + bb.y};
                *(float2*)(out + (size_t)m * Ff + f) = r;
            }
        }
}

// ------------------------------------------------------------------
extern "C" void kernel_launch(void* const* d_in, const int* in_sizes, int n_in,
                              void* d_out, int out_size) {
    const float* x    = (const float*)d_in[0];
    const float* W    = (const float*)d_in[1];
    const float* bias = (const float*)d_in[2];
    float* out        = (float*)d_out;

    wt_kernel<<<(Ff * Kk + 255) / 256, 256>>>(W);
    rot_kernel<<<Pp / 4, 128>>>(x);
    gemm_mma_kernel<<<Ppad / 128, 256>>>(bias, out);
}